// round 14
// baseline (speedup 1.0000x reference)
#include <cuda_runtime.h>
#include <cstdint>

#define SEQ   512
#define BATCH 512
#define IDIM  300
#define HDIM  300
#define NP    320            // padded hidden for XP layout
#define JH    152            // per-CTA j-half in scan
#define MTOT  (SEQ*BATCH)

// GEMM tiling: 64x160 tile, 256 threads, 4m x 10n per thread (40 acc regs)
#define BM 64
#define BN 160
#define BK 20
#define GTH 256

// scan: 608 threads = 8 k-octants x (38 j-quads x 2 halves); 4j x 4b x 38k each
#define STH    608
#define KOCT   8
#define SKCH   38                 // k rows per octant (304 total, permuted)
#define KROWS  304
#define HB     (KROWS*8)          // one h buffer: [304 rows][8 b] floats
#define WSZ    (KROWS*JH)         // 46208 floats
#define PSTR   616                // padded PART slot stride (u64)
#define XSTR   154                // XPS row stride (floats, even for STS.64)
#define TXBYTES 4864              // per-step remote h bytes (152j x 8b x 4B)

// -------- scratch (static device global; no allocations) --------
__device__ float g_XP[(long long)MTOT * NP];     // ~335 MB

// -------- f32x2 helpers (Blackwell packed fp32, PTX-only) --------
__device__ __forceinline__ unsigned long long bcast2(float v) {
    unsigned long long r;
    asm("mov.b64 %0, {%1, %1};" : "=l"(r) : "f"(v));
    return r;
}
__device__ __forceinline__ void ffma2(unsigned long long& d, unsigned long long a, unsigned long long b) {
    asm("fma.rn.f32x2 %0, %1, %2, %3;" : "=l"(d) : "l"(a), "l"(b), "l"(d));
}
__device__ __forceinline__ void fadd2(unsigned long long& d, unsigned long long a) {
    asm("add.rn.f32x2 %0, %1, %2;" : "=l"(d) : "l"(d), "l"(a));
}
__device__ __forceinline__ void unpack2(unsigned long long v, float& lo, float& hi) {
    asm("mov.b64 {%0, %1}, %2;" : "=f"(lo), "=f"(hi) : "l"(v));
}
__device__ __forceinline__ uint32_t smem_u32(const void* p) {
    uint32_t a;
    asm("{ .reg .u64 t; cvta.to.shared.u64 t, %1; cvt.u32.u64 %0, t; }" : "=r"(a) : "l"(p));
    return a;
}
// fast tanh: 1 - 2/(exp(2x)+1); saturates correctly at +-inf
__device__ __forceinline__ float fast_tanh(float x) {
    float e = __expf(2.0f * x);
    return 1.0f - __fdividef(2.0f, e + 1.0f);
}
// async remote store: data lands in peer smem, credits peer's mbarrier tx-count
__device__ __forceinline__ void dsmem_st_async64(uint32_t addr, uint32_t mbar, unsigned peer,
                                                 float lo, float hi) {
    asm volatile("{ .reg .b32 ra, rm; .reg .b64 d; mov.b64 d, {%3,%4}; "
                 "mapa.shared::cluster.u32 ra, %0, %2; "
                 "mapa.shared::cluster.u32 rm, %1, %2; "
                 "st.async.shared::cluster.mbarrier::complete_tx::bytes.b64 [ra], d, [rm]; }"
                 :: "r"(addr), "r"(mbar), "r"(peer), "f"(lo), "f"(hi) : "memory");
}

// -------- x_proj GEMM: XP[m][j] = IN[m][:] . W_ih[j][:] + b_ih[j] + b_hh[j] --------
__global__ __launch_bounds__(GTH, 3) void gemm_xproj(const float* __restrict__ IN,
                                                     const float* __restrict__ Wih,
                                                     const float* __restrict__ bih,
                                                     const float* __restrict__ bhh) {
    __shared__ float As[BK][BM + 4];  // [k][m], padded
    __shared__ float Bs[BK][BN];      // [k][n], n contiguous
    int tid = threadIdx.x;
    int m0 = blockIdx.y * BM;
    int n0 = blockIdx.x * BN;
    int mth = tid >> 4, nth = tid & 15;   // 16 x 16
    int tm0 = mth * 4, tn0 = nth * 10;

    unsigned long long acc[4][5];
    #pragma unroll
    for (int i = 0; i < 4; i++)
        #pragma unroll
        for (int u = 0; u < 5; u++) acc[i][u] = 0ull;

    for (int kk = 0; kk < IDIM; kk += BK) {
        #pragma unroll
        for (int l = 0; l < (BM * BK) / GTH; l++) {
            int idx = tid + l * GTH;
            int m = idx / BK, k = idx % BK;
            As[k][m] = IN[(long long)(m0 + m) * IDIM + kk + k];
        }
        #pragma unroll
        for (int slot = tid; slot < BN * (BK / 4); slot += GTH) {
            int n = slot % BN, kg = slot / BN;
            int gn = n0 + n;
            float4 v = make_float4(0.f, 0.f, 0.f, 0.f);
            if (gn < HDIM)
                v = *(const float4*)&Wih[(long long)gn * IDIM + kk + kg * 4];
            Bs[kg * 4 + 0][n] = v.x;
            Bs[kg * 4 + 1][n] = v.y;
            Bs[kg * 4 + 2][n] = v.z;
            Bs[kg * 4 + 3][n] = v.w;
        }
        __syncthreads();
        #pragma unroll
        for (int k = 0; k < BK; k++) {
            float4 av = *(const float4*)&As[k][tm0];
            const unsigned long long* Bk = (const unsigned long long*)&Bs[k][tn0];
            unsigned long long b0 = Bk[0], b1 = Bk[1], b2 = Bk[2], b3 = Bk[3], b4 = Bk[4];
            unsigned long long a0 = bcast2(av.x), a1 = bcast2(av.y);
            unsigned long long a2 = bcast2(av.z), a3 = bcast2(av.w);
            ffma2(acc[0][0], a0, b0); ffma2(acc[0][1], a0, b1); ffma2(acc[0][2], a0, b2);
            ffma2(acc[0][3], a0, b3); ffma2(acc[0][4], a0, b4);
            ffma2(acc[1][0], a1, b0); ffma2(acc[1][1], a1, b1); ffma2(acc[1][2], a1, b2);
            ffma2(acc[1][3], a1, b3); ffma2(acc[1][4], a1, b4);
            ffma2(acc[2][0], a2, b0); ffma2(acc[2][1], a2, b1); ffma2(acc[2][2], a2, b2);
            ffma2(acc[2][3], a2, b3); ffma2(acc[2][4], a2, b4);
            ffma2(acc[3][0], a3, b0); ffma2(acc[3][1], a3, b1); ffma2(acc[3][2], a3, b2);
            ffma2(acc[3][3], a3, b3); ffma2(acc[3][4], a3, b4);
        }
        __syncthreads();
    }
    float bias[10];
    #pragma unroll
    for (int u = 0; u < 10; u++) {
        int gn = n0 + tn0 + u;
        bias[u] = (gn < HDIM) ? (bih[gn] + bhh[gn]) : 0.f;
    }
    #pragma unroll
    for (int i = 0; i < 4; i++) {
        long long row = (long long)(m0 + tm0 + i) * NP + n0 + tn0;
        #pragma unroll
        for (int u = 0; u < 5; u++) {
            float lo, hi; unpack2(acc[i][u], lo, hi);
            float2 v = make_float2(lo + bias[2 * u], hi + bias[2 * u + 1]);
            *(float2*)&g_XP[row + 2 * u] = v;
        }
    }
}

// -------- recurrent scan: 64 clusters x 2 CTAs, 8 batch per cluster --------
// As R13 (permuted-k, 4j x 4b x 38k, 2-phase PART tail) plus:
//  * XPS staging: all 608 threads do ONE coalesced float2 LDG of xp into smem
//    ([8 b][154] rows); reducers read via LDS.32 (kills the scattered 8-LDG
//    gather that dominated L1 wavefronts).
//  * st.async h delivery: reducers' peer stores credit the peer's mbarrier
//    tx-count directly (expect_tx = 4864 B/step). Remote warps wake on byte
//    arrival instead of after the producer's full tail + arrive. Two
//    alternating mbarriers (step parity) keep phases separated by 2 steps.
__global__ __cluster_dims__(2, 1, 1) __launch_bounds__(STH, 1)
void scan_kernel(const float* __restrict__ Whh, float* __restrict__ out) {
    extern __shared__ float sm[];
    float* WT = sm;                                            // [304][152]
    float* H  = sm + WSZ;                                      // [2][304][8]
    unsigned long long* PART = (unsigned long long*)(H + 2 * HB);   // [4][PSTR]
    float* XPS = (float*)(PART + 4 * PSTR);                    // [8][XSTR]
    unsigned long long* mbars = (unsigned long long*)(XPS + 8 * XSTR);  // [2]

    int tid = threadIdx.x;
    unsigned rank;
    asm("mov.u32 %0, %%cluster_ctarank;" : "=r"(rank));
    int cid = blockIdx.x >> 1;
    unsigned peer = rank ^ 1u;

    if (tid == 0) {
        asm volatile("mbarrier.init.shared.b64 [%0], 1;" :: "r"(smem_u32(&mbars[0])) : "memory");
        asm volatile("mbarrier.init.shared.b64 [%0], 1;" :: "r"(smem_u32(&mbars[1])) : "memory");
    }
    // WT[kloc][j] = Whh[rank*152+j][kglob]; kloc<152 own k, >=152 peer k
    for (int idx = tid; idx < JH * KROWS; idx += STH) {
        int j = idx / KROWS, kloc = idx % KROWS;
        int jg = rank * JH + j;
        int kg = (kloc < JH) ? (rank * JH + kloc) : (peer * JH + (kloc - JH));
        float v = 0.f;
        if (jg < HDIM && kg < HDIM) v = Whh[(long long)jg * HDIM + kg];
        WT[kloc * JH + j] = v;
    }
    for (int i = tid; i < 2 * HB; i += STH) H[i] = 0.f;

    // MAC-role: tid = koct*76 + (jq*2 + half)
    int koct = tid / 76, lid2 = tid % 76;
    int jq = lid2 >> 1, half = lid2 & 1;
    int J0 = jq * 4, b0 = half * 4;
    int kstart = koct * SKCH;
    const float* Wp0 = WT + kstart * JH + J0;
    bool remote_warp = (tid >> 5) >= 9;        // warps with koct>=4 lanes
    bool reducer = (koct < 2);
    int rr = koct;                              // reducer's row-in-phase

    // XPS loader role: b = koct (0..7), j-pair = lid2 (coalesced float2 LDG)
    const float* xldg = g_XP + (long long)(cid * 8 + koct) * NP + rank * JH + lid2 * 2;
    float* xsts = XPS + koct * XSTR + lid2 * 2;

    uint32_t hbase32 = smem_u32(H);
    uint32_t mbar32 = smem_u32(&mbars[0]);

    __syncthreads();
    asm volatile("barrier.cluster.arrive.aligned;" ::: "memory");
    asm volatile("barrier.cluster.wait.aligned;" ::: "memory");

    int p = 0;
    for (int t = 0; t < SEQ; t++) {
        // stage this step's xp into XPS (coalesced; consumed in tail)
        float2 xv = *(const float2*)(xldg + (long long)t * BATCH * NP);

        // remote warps (incl. warp 18) wait for peer's step-(t-1) h bytes
        if (t > 0 && remote_warp) {
            uint32_t mb = mbar32 + (uint32_t)(((t - 1) & 1) * 8);
            unsigned ph = (unsigned)(((t - 1) >> 1) & 1);
            uint32_t done;
            asm volatile("{ .reg .pred p; "
                         "mbarrier.try_wait.parity.acquire.cluster.shared::cta.b64 p, [%1], %2; "
                         "selp.b32 %0, 1, 0, p; }"
                         : "=r"(done) : "r"(mb), "r"(ph) : "memory");
            if (!done) {
                asm volatile("{ .reg .pred P1; "
                             "WL%=: mbarrier.try_wait.parity.acquire.cluster.shared::cta.b64 P1, [%0], %1, 0x989680; "
                             "@P1 bra.uni WD%=; bra.uni WL%=; WD%=: }"
                             :: "r"(mb), "r"(ph) : "memory");
            }
        }
        // one lane (in an already-waiting remote warp) arms this step's mbar
        if (tid == 576) {
            asm volatile("mbarrier.arrive.expect_tx.shared::cta.b64 _, [%0], %1;"
                         :: "r"(mbar32 + (uint32_t)((t & 1) * 8)), "r"((uint32_t)TXBYTES)
                         : "memory");
        }
        *(float2*)xsts = xv;

        // MAC: 4j x 4b x 38k
        unsigned long long A[4][2];
        #pragma unroll
        for (int i = 0; i < 4; i++) { A[i][0] = 0ull; A[i][1] = 0ull; }
        const float* Wp = Wp0;
        const float* hp = H + p * HB + kstart * 8 + b0;
        #pragma unroll
        for (int kk = 0; kk < SKCH; kk++) {
            float4 w = *(const float4*)(Wp + kk * JH);
            ulonglong2 hv = *(const ulonglong2*)(hp + kk * 8);
            unsigned long long w0 = bcast2(w.x);
            unsigned long long w1 = bcast2(w.y);
            unsigned long long w2 = bcast2(w.z);
            unsigned long long w3 = bcast2(w.w);
            ffma2(A[0][0], w0, hv.x); ffma2(A[0][1], w0, hv.y);
            ffma2(A[1][0], w1, hv.x); ffma2(A[1][1], w1, hv.y);
            ffma2(A[2][0], w2, hv.x); ffma2(A[2][1], w2, hv.y);
            ffma2(A[3][0], w3, hv.x); ffma2(A[3][1], w3, hv.y);
        }

        uint32_t txmb = mbar32 + (uint32_t)((t & 1) * 8);

        // ---- phase 0: rows J0+0, J0+1 ----
        PART[0 * PSTR + tid] = A[0][0];
        PART[1 * PSTR + tid] = A[0][1];
        PART[2 * PSTR + tid] = A[1][0];
        PART[3 * PSTR + tid] = A[1][1];
        __syncthreads();
        float xa[4], xb[4];
        if (reducer) {
            int rowa = J0 + rr, rowb = J0 + 2 + rr;
            #pragma unroll
            for (int bi = 0; bi < 4; bi++) {
                xa[bi] = XPS[(b0 + bi) * XSTR + rowa];
                xb[bi] = XPS[(b0 + bi) * XSTR + rowb];
            }
            int row = rowa;
            #pragma unroll
            for (int bp = 0; bp < 2; bp++) {
                const unsigned long long* src = PART + (rr * 2 + bp) * PSTR + lid2;
                unsigned long long acc = src[0];
                #pragma unroll
                for (int q = 1; q < KOCT; q++) fadd2(acc, src[q * 76]);
                float v0, v1; unpack2(acc, v0, v1);
                float h0 = fast_tanh(xa[2 * bp] + v0);
                float h1 = fast_tanh(xa[2 * bp + 1] + v1);
                int off = (1 - p) * HB + row * 8 + b0 + 2 * bp;
                *(float2*)(H + off) = make_float2(h0, h1);
                dsmem_st_async64(hbase32 + ((1 - p) * HB + (JH + row) * 8 + b0 + 2 * bp) * 4,
                                 txmb, peer, h0, h1);
            }
        }
        __syncthreads();
        // ---- phase 1: rows J0+2, J0+3 ----
        PART[0 * PSTR + tid] = A[2][0];
        PART[1 * PSTR + tid] = A[2][1];
        PART[2 * PSTR + tid] = A[3][0];
        PART[3 * PSTR + tid] = A[3][1];
        __syncthreads();
        if (reducer) {
            int row = J0 + 2 + rr;
            #pragma unroll
            for (int bp = 0; bp < 2; bp++) {
                const unsigned long long* src = PART + (rr * 2 + bp) * PSTR + lid2;
                unsigned long long acc = src[0];
                #pragma unroll
                for (int q = 1; q < KOCT; q++) fadd2(acc, src[q * 76]);
                float v0, v1; unpack2(acc, v0, v1);
                float h0 = fast_tanh(xb[2 * bp] + v0);
                float h1 = fast_tanh(xb[2 * bp + 1] + v1);
                int off = (1 - p) * HB + row * 8 + b0 + 2 * bp;
                *(float2*)(H + off) = make_float2(h0, h1);
                dsmem_st_async64(hbase32 + ((1 - p) * HB + (JH + row) * 8 + b0 + 2 * bp) * 4,
                                 txmb, peer, h0, h1);
            }
        }
        __syncthreads();   // local H[1-p] writes visible to next step's local MAC
        p ^= 1;
    }

    // final h: own rows [0,152) of H[p] -> out
    const float* Hf = H + p * HB;
    int cb0 = cid * 8;
    for (int idx = tid; idx < 8 * JH; idx += STH) {
        int b = idx / JH, jj = idx % JH;
        int j = rank * JH + jj;
        if (j < HDIM) out[(long long)(cb0 + b) * HDIM + j] = Hf[jj * 8 + b];
    }
    // no CTA may exit while peer st.async targeting our smem could be in flight
    asm volatile("barrier.cluster.arrive.aligned;" ::: "memory");
    asm volatile("barrier.cluster.wait.aligned;" ::: "memory");
}

extern "C" void kernel_launch(void* const* d_in, const int* in_sizes, int n_in,
                              void* d_out, int out_size) {
    const float* IN  = (const float*)d_in[0];
    const float* Wih = (const float*)d_in[1];
    const float* Whh = (const float*)d_in[2];
    const float* bih = (const float*)d_in[3];
    const float* bhh = (const float*)d_in[4];
    float* out = (float*)d_out;

    dim3 g(NP / BN, MTOT / BM);   // (2, 4096)
    gemm_xproj<<<g, GTH>>>(IN, Wih, bih, bhh);

    // smem: WT 184832 + H 19456 + PART 19712 + XPS 4928 + mbars 16 = 228944 B
    size_t smem = (size_t)WSZ * 4 + (size_t)2 * HB * 4 + (size_t)4 * PSTR * 8
                + (size_t)8 * XSTR * 4 + 16;
    cudaFuncSetAttribute(scan_kernel, cudaFuncAttributeMaxDynamicSharedMemorySize, (int)smem);
    scan_kernel<<<128, STH, smem>>>(Whh, out);
}

// round 15
// speedup vs baseline: 1.0179x; 1.0179x over previous
#include <cuda_runtime.h>
#include <cstdint>

#define SEQ   512
#define BATCH 512
#define IDIM  300
#define HDIM  300
#define NP    320            // padded hidden for XP layout
#define JH    152            // per-CTA j-half in scan
#define MTOT  (SEQ*BATCH)

// GEMM tiling: 64x160 tile, 256 threads, 4m x (5 strided n-pairs) per thread
#define BM 64
#define BN 160
#define BK 20
#define GTH 256

// scan (R12 config): 608 threads = 4 k-quarters x (76 j-pairs x 2 halves)
#define STH    608
#define SKQ    4
#define SKCH   76                 // k rows per quarter (304 total, permuted)
#define KROWS  304
#define HB     (KROWS*8)          // one h buffer: [304 rows][8 b] floats
#define WSZ    (KROWS*JH)         // 46208 floats
#define PSTR   612                // padded PART slot stride (u64)
#define XSTR   154                // XPS row stride (floats, 8B-aligned rows)

// -------- scratch (static device global; no allocations) --------
__device__ float g_XP[(long long)MTOT * NP];     // ~335 MB

// -------- f32x2 helpers (Blackwell packed fp32, PTX-only) --------
__device__ __forceinline__ unsigned long long bcast2(float v) {
    unsigned long long r;
    asm("mov.b64 %0, {%1, %1};" : "=l"(r) : "f"(v));
    return r;
}
__device__ __forceinline__ void ffma2(unsigned long long& d, unsigned long long a, unsigned long long b) {
    asm("fma.rn.f32x2 %0, %1, %2, %3;" : "=l"(d) : "l"(a), "l"(b), "l"(d));
}
__device__ __forceinline__ void fadd2(unsigned long long& d, unsigned long long a) {
    asm("add.rn.f32x2 %0, %1, %2;" : "=l"(d) : "l"(d), "l"(a));
}
__device__ __forceinline__ void unpack2(unsigned long long v, float& lo, float& hi) {
    asm("mov.b64 {%0, %1}, %2;" : "=f"(lo), "=f"(hi) : "l"(v));
}
__device__ __forceinline__ uint32_t smem_u32(const void* p) {
    uint32_t a;
    asm("{ .reg .u64 t; cvta.to.shared.u64 t, %1; cvt.u32.u64 %0, t; }" : "=r"(a) : "l"(p));
    return a;
}
// fast tanh: 1 - 2/(exp(2x)+1); saturates correctly at +-inf
__device__ __forceinline__ float fast_tanh(float x) {
    float e = __expf(2.0f * x);
    return 1.0f - __fdividef(2.0f, e + 1.0f);
}
__device__ __forceinline__ void dsmem_st64(uint32_t addr, unsigned peer, float lo, float hi) {
    asm volatile("{ .reg .b32 pa; .reg .b64 d; mov.b64 d, {%2,%3}; "
                 "mapa.shared::cluster.u32 pa, %0, %1; st.shared::cluster.b64 [pa], d; }"
                 :: "r"(addr), "r"(peer), "f"(lo), "f"(hi) : "memory");
}

// -------- x_proj GEMM: XP[m][j] = IN[m][:] . W_ih[j][:] + b_ih[j] + b_hh[j] --------
// Thread owns n-column PAIRS at n = nth*2 + 32u (u=0..4): each Bs LDS.64 is
// 16 lanes x 8B CONTIGUOUS = 1 wavefront (the old 10-consecutive-n tile made
// every Bs load span 640B = 5 wavefronts -> gemm was LSU-saturated at 1.3ms).
// (256,2): 128-reg cap, no spill.
__global__ __launch_bounds__(GTH, 2) void gemm_xproj(const float* __restrict__ IN,
                                                     const float* __restrict__ Wih,
                                                     const float* __restrict__ bih,
                                                     const float* __restrict__ bhh) {
    __shared__ float As[BK][BM + 4];  // [k][m], padded
    __shared__ float Bs[BK][BN];      // [k][n], n contiguous
    int tid = threadIdx.x;
    int m0 = blockIdx.y * BM;
    int n0 = blockIdx.x * BN;
    int mth = tid >> 4, nth = tid & 15;   // 16 x 16
    int tm0 = mth * 4, tn0 = nth * 2;     // pair base; cols tn0+32u, +1

    unsigned long long acc[4][5];
    #pragma unroll
    for (int i = 0; i < 4; i++)
        #pragma unroll
        for (int u = 0; u < 5; u++) acc[i][u] = 0ull;

    for (int kk = 0; kk < IDIM; kk += BK) {
        #pragma unroll
        for (int l = 0; l < (BM * BK) / GTH; l++) {
            int idx = tid + l * GTH;
            int m = idx / BK, k = idx % BK;
            As[k][m] = IN[(long long)(m0 + m) * IDIM + kk + k];
        }
        #pragma unroll
        for (int slot = tid; slot < BN * (BK / 4); slot += GTH) {
            int n = slot % BN, kg = slot / BN;
            int gn = n0 + n;
            float4 v = make_float4(0.f, 0.f, 0.f, 0.f);
            if (gn < HDIM)
                v = *(const float4*)&Wih[(long long)gn * IDIM + kk + kg * 4];
            Bs[kg * 4 + 0][n] = v.x;
            Bs[kg * 4 + 1][n] = v.y;
            Bs[kg * 4 + 2][n] = v.z;
            Bs[kg * 4 + 3][n] = v.w;
        }
        __syncthreads();
        #pragma unroll
        for (int k = 0; k < BK; k++) {
            float4 av = *(const float4*)&As[k][tm0];
            unsigned long long b0 = *(const unsigned long long*)&Bs[k][tn0];
            unsigned long long b1 = *(const unsigned long long*)&Bs[k][tn0 + 32];
            unsigned long long b2 = *(const unsigned long long*)&Bs[k][tn0 + 64];
            unsigned long long b3 = *(const unsigned long long*)&Bs[k][tn0 + 96];
            unsigned long long b4 = *(const unsigned long long*)&Bs[k][tn0 + 128];
            unsigned long long a0 = bcast2(av.x), a1 = bcast2(av.y);
            unsigned long long a2 = bcast2(av.z), a3 = bcast2(av.w);
            ffma2(acc[0][0], a0, b0); ffma2(acc[0][1], a0, b1); ffma2(acc[0][2], a0, b2);
            ffma2(acc[0][3], a0, b3); ffma2(acc[0][4], a0, b4);
            ffma2(acc[1][0], a1, b0); ffma2(acc[1][1], a1, b1); ffma2(acc[1][2], a1, b2);
            ffma2(acc[1][3], a1, b3); ffma2(acc[1][4], a1, b4);
            ffma2(acc[2][0], a2, b0); ffma2(acc[2][1], a2, b1); ffma2(acc[2][2], a2, b2);
            ffma2(acc[2][3], a2, b3); ffma2(acc[2][4], a2, b4);
            ffma2(acc[3][0], a3, b0); ffma2(acc[3][1], a3, b1); ffma2(acc[3][2], a3, b2);
            ffma2(acc[3][3], a3, b3); ffma2(acc[3][4], a3, b4);
        }
        __syncthreads();
    }
    float bias[10];
    #pragma unroll
    for (int u = 0; u < 5; u++) {
        int gn = n0 + tn0 + 32 * u;
        bias[2 * u]     = (gn < HDIM)     ? (bih[gn] + bhh[gn])         : 0.f;
        bias[2 * u + 1] = (gn + 1 < HDIM) ? (bih[gn + 1] + bhh[gn + 1]) : 0.f;
    }
    #pragma unroll
    for (int i = 0; i < 4; i++) {
        long long row = (long long)(m0 + tm0 + i) * NP + n0 + tn0;
        #pragma unroll
        for (int u = 0; u < 5; u++) {
            float lo, hi; unpack2(acc[i][u], lo, hi);
            float2 v = make_float2(lo + bias[2 * u], hi + bias[2 * u + 1]);
            *(float2*)&g_XP[row + 32 * u] = v;
        }
    }
}

// -------- recurrent scan: 64 clusters x 2 CTAs, 8 batch per cluster --------
// Exact R12 structure (best measured: permuted-k, 2j x 4b x 76k, single-phase
// full-parallel tail, dsmem_st64 + single release-arrive handshake) plus XPS:
// all 608 threads stage this step's xp with ONE coalesced float2 LDG -> smem;
// reducers read it via LDS.32 after the existing pre-reduce syncthreads.
__global__ __cluster_dims__(2, 1, 1) __launch_bounds__(STH, 1)
void scan_kernel(const float* __restrict__ Whh, float* __restrict__ out) {
    extern __shared__ float sm[];
    float* WT = sm;                                           // [304][152] permuted-k
    float* H  = sm + WSZ;                                     // [2][304][8]
    unsigned long long* PART = (unsigned long long*)(H + 2 * HB);  // [4][PSTR]
    float* XPS = (float*)(PART + 4 * PSTR);                   // [8][XSTR]
    unsigned long long* mbarp = (unsigned long long*)(XPS + 8 * XSTR);

    int tid = threadIdx.x;
    unsigned rank;
    asm("mov.u32 %0, %%cluster_ctarank;" : "=r"(rank));
    int cid = blockIdx.x >> 1;
    unsigned peer = rank ^ 1u;

    if (tid == 0) {
        asm volatile("mbarrier.init.shared.b64 [%0], 1;"
                     :: "r"(smem_u32(mbarp)) : "memory");
    }
    // WT[kloc][j] = Whh[rank*152+j][kglob]; kloc<152 own k, >=152 peer k
    for (int idx = tid; idx < JH * KROWS; idx += STH) {
        int j = idx / KROWS, kloc = idx % KROWS;
        int jg = rank * JH + j;
        int kg = (kloc < JH) ? (rank * JH + kloc) : (peer * JH + (kloc - JH));
        float v = 0.f;
        if (jg < HDIM && kg < HDIM) v = Whh[(long long)jg * HDIM + kg];
        WT[kloc * JH + j] = v;
    }
    for (int i = tid; i < 2 * HB; i += STH) H[i] = 0.f;

    // MAC-role indices: tid = kq*152 + jp*2 + half
    int kq = tid / 152, lid2 = tid % 152;
    int jp = lid2 >> 1, half = lid2 & 1;
    int j0 = jp * 2;
    int kstart = kq * SKCH;
    const float* Wp0 = WT + kstart * JH + j0;
    bool remote_warp = (tid >> 5) >= 9;      // warps with kq>=2 lanes

    // reduce-role indices: one u64 output (row j_out, batch pair bq)
    int j_out = tid >> 2, bq = tid & 3;
    int lid2_s = (j_out >> 1) * 2 + (bq >> 1);   // producer lane within kq block
    int s_slot = (j_out & 1) * 2 + (bq & 1);     // producer acc slot

    // XPS loader role: batch lb (0..7), j-pair lj (coalesced float2 LDG)
    int lb = tid / 76, lj = tid % 76;
    const float* xldg = g_XP + (long long)(cid * 8 + lb) * NP + rank * JH + lj * 2;
    float* xsts = XPS + lb * XSTR + lj * 2;

    uint32_t hbase32 = smem_u32(H);
    uint32_t mbar32 = smem_u32(mbarp);

    __syncthreads();
    asm volatile("barrier.cluster.arrive.aligned;" ::: "memory");
    asm volatile("barrier.cluster.wait.aligned;" ::: "memory");

    int p = 0;
    for (int t = 0; t < SEQ; t++) {
        // stage xp for this step (coalesced LDG; consumed after the tail sync)
        float2 xv = *(const float2*)(xldg + (long long)t * BATCH * NP);
        *(float2*)xsts = xv;

        // remote warps wait for peer's step-(t-1) h-half; local warps proceed
        if (t > 0 && remote_warp) {
            unsigned ph = (unsigned)((t - 1) & 1);
            uint32_t done;
            asm volatile("{ .reg .pred p; "
                         "mbarrier.try_wait.parity.acquire.cluster.shared::cta.b64 p, [%1], %2; "
                         "selp.b32 %0, 1, 0, p; }"
                         : "=r"(done) : "r"(mbar32), "r"(ph) : "memory");
            if (!done) {
                asm volatile("{ .reg .pred P1; "
                             "WL%=: mbarrier.try_wait.parity.acquire.cluster.shared::cta.b64 P1, [%0], %1, 0x989680; "
                             "@P1 bra.uni WD%=; bra.uni WL%=; WD%=: }"
                             :: "r"(mbar32), "r"(ph) : "memory");
            }
        }

        // MAC over this thread's k-quarter (2j x 4b x 76k)
        unsigned long long A00 = 0, A01 = 0, A10 = 0, A11 = 0;
        const float* Wp = Wp0;
        const float* hp = H + p * HB + kstart * 8 + half * 4;
        #pragma unroll 4
        for (int kk = 0; kk < SKCH; kk++) {
            float2 w = *(const float2*)(Wp + kk * JH);
            ulonglong2 hv = *(const ulonglong2*)(hp + kk * 8);
            unsigned long long w0 = bcast2(w.x);
            unsigned long long w1 = bcast2(w.y);
            ffma2(A00, w0, hv.x); ffma2(A01, w0, hv.y);
            ffma2(A10, w1, hv.x); ffma2(A11, w1, hv.y);
        }
        PART[0 * PSTR + tid] = A00;
        PART[1 * PSTR + tid] = A01;
        PART[2 * PSTR + tid] = A10;
        PART[3 * PSTR + tid] = A11;
        __syncthreads();

        // reduce 4 k-quarter partials for output (j_out, batches 2bq, 2bq+1)
        const unsigned long long* src = PART + s_slot * PSTR + lid2_s;
        unsigned long long acc = src[0];
        fadd2(acc, src[152]);
        fadd2(acc, src[304]);
        fadd2(acc, src[456]);
        float x0 = XPS[(bq * 2) * XSTR + j_out];
        float x1 = XPS[(bq * 2 + 1) * XSTR + j_out];
        float v0, v1;
        unpack2(acc, v0, v1);
        float h0 = fast_tanh(x0 + v0);
        float h1 = fast_tanh(x1 + v1);
        int off = (1 - p) * HB + j_out * 8 + bq * 2;          // own region row
        *(float2*)(H + off) = make_float2(h0, h1);
        uint32_t rdst = hbase32 + ((1 - p) * HB + (JH + j_out) * 8 + bq * 2) * 4;
        dsmem_st64(rdst, peer, h0, h1);                       // peer's [152+j] row

        __syncthreads();   // local H writes + DSMEM stores ordered before arrive
        if (tid == 0) {
            asm volatile("{ .reg .b32 pa; mapa.shared::cluster.u32 pa, %0, %1; "
                         "mbarrier.arrive.release.cluster.shared::cluster.b64 _, [pa]; }"
                         :: "r"(mbar32), "r"(peer) : "memory");
        }
        p ^= 1;
    }

    // final h: own rows [0,152) of H[p] -> out
    const float* Hf = H + p * HB;
    int cb0 = cid * 8;
    for (int idx = tid; idx < 8 * JH; idx += STH) {
        int b = idx / JH, jj = idx % JH;
        int j = rank * JH + jj;
        if (j < HDIM) out[(long long)(cb0 + b) * HDIM + j] = Hf[jj * 8 + b];
    }
    asm volatile("barrier.cluster.arrive.aligned;" ::: "memory");
    asm volatile("barrier.cluster.wait.aligned;" ::: "memory");
}

extern "C" void kernel_launch(void* const* d_in, const int* in_sizes, int n_in,
                              void* d_out, int out_size) {
    const float* IN  = (const float*)d_in[0];
    const float* Wih = (const float*)d_in[1];
    const float* Whh = (const float*)d_in[2];
    const float* bih = (const float*)d_in[3];
    const float* bhh = (const float*)d_in[4];
    float* out = (float*)d_out;

    dim3 g(NP / BN, MTOT / BM);   // (2, 4096)
    gemm_xproj<<<g, GTH>>>(IN, Wih, bih, bhh);

    // smem: WT 184832 + H 19456 + PART 19584 + XPS 4928 + mbar 8 = 228808 B
    size_t smem = (size_t)WSZ * 4 + (size_t)2 * HB * 4 + (size_t)4 * PSTR * 8
                + (size_t)8 * XSTR * 4 + 8;
    cudaFuncSetAttribute(scan_kernel, cudaFuncAttributeMaxDynamicSharedMemorySize, (int)smem);
    scan_kernel<<<128, STH, smem>>>(Whh, out);
}

// round 16
// speedup vs baseline: 1.1080x; 1.0885x over previous
#include <cuda_runtime.h>
#include <cstdint>

#define SEQ   512
#define BATCH 512
#define IDIM  300
#define HDIM  300
#define NP    320            // padded hidden for XP layout
#define JH    152            // per-CTA j-half in scan
#define MTOT  (SEQ*BATCH)

// GEMM tiling: 64x160 tile, 256 threads, 4m x (5 strided n-pairs) per thread
#define BM 64
#define BN 160
#define BK 20
#define GTH 256
#define NKT (IDIM/BK)        // 15 k-tiles

// scan (R12 config): 608 threads = 4 k-quarters x (76 j-pairs x 2 halves)
#define STH    608
#define SKQ    4
#define SKCH   76                 // k rows per quarter (304 total, permuted)
#define KROWS  304
#define HB     (KROWS*8)          // one h buffer: [304 rows][8 b] floats
#define WSZ    (KROWS*JH)         // 46208 floats
#define PSTR   612                // padded PART slot stride (u64)
#define XSTR   154                // XPS row stride (floats, 8B-aligned rows)

// -------- scratch (static device global; no allocations) --------
__device__ float g_XP[(long long)MTOT * NP];     // ~335 MB

// -------- f32x2 helpers (Blackwell packed fp32, PTX-only) --------
__device__ __forceinline__ unsigned long long bcast2(float v) {
    unsigned long long r;
    asm("mov.b64 %0, {%1, %1};" : "=l"(r) : "f"(v));
    return r;
}
__device__ __forceinline__ void ffma2(unsigned long long& d, unsigned long long a, unsigned long long b) {
    asm("fma.rn.f32x2 %0, %1, %2, %3;" : "=l"(d) : "l"(a), "l"(b), "l"(d));
}
__device__ __forceinline__ void fadd2(unsigned long long& d, unsigned long long a) {
    asm("add.rn.f32x2 %0, %1, %2;" : "=l"(d) : "l"(d), "l"(a));
}
__device__ __forceinline__ void unpack2(unsigned long long v, float& lo, float& hi) {
    asm("mov.b64 {%0, %1}, %2;" : "=f"(lo), "=f"(hi) : "l"(v));
}
__device__ __forceinline__ uint32_t smem_u32(const void* p) {
    uint32_t a;
    asm("{ .reg .u64 t; cvta.to.shared.u64 t, %1; cvt.u32.u64 %0, t; }" : "=r"(a) : "l"(p));
    return a;
}
// fast tanh: 1 - 2/(exp(2x)+1); saturates correctly at +-inf
__device__ __forceinline__ float fast_tanh(float x) {
    float e = __expf(2.0f * x);
    return 1.0f - __fdividef(2.0f, e + 1.0f);
}
__device__ __forceinline__ void dsmem_st64(uint32_t addr, unsigned peer, float lo, float hi) {
    asm volatile("{ .reg .b32 pa; .reg .b64 d; mov.b64 d, {%2,%3}; "
                 "mapa.shared::cluster.u32 pa, %0, %1; st.shared::cluster.b64 [pa], d; }"
                 :: "r"(addr), "r"(peer), "f"(lo), "f"(hi) : "memory");
}

// -------- x_proj GEMM: XP[m][j] = IN[m][:] . W_ih[j][:] + b_ih[j] + b_hh[j] --------
// Software-pipelined: tile t+1 is prefetched into registers right after the
// post-store sync, so its DRAM latency (streamed IN) drains under tile t's
// 400-FFMA2 compute section instead of being exposed at the tile boundary
// (measured gemm was 1.28ms vs 0.77ms FFMA2 floor = boundary-latency bound).
__global__ __launch_bounds__(GTH, 2) void gemm_xproj(const float* __restrict__ IN,
                                                     const float* __restrict__ Wih,
                                                     const float* __restrict__ bih,
                                                     const float* __restrict__ bhh) {
    __shared__ float As[BK][BM + 4];  // [k][m], padded
    __shared__ float Bs[BK][BN];      // [k][n], n contiguous
    int tid = threadIdx.x;
    int m0 = blockIdx.y * BM;
    int n0 = blockIdx.x * BN;
    int mth = tid >> 4, nth = tid & 15;   // 16 x 16
    int tm0 = mth * 4, tn0 = nth * 2;     // strided n-pairs: cols tn0+32u

    unsigned long long acc[4][5];
    #pragma unroll
    for (int i = 0; i < 4; i++)
        #pragma unroll
        for (int u = 0; u < 5; u++) acc[i][u] = 0ull;

    // prefetch registers
    float  aPre[5];
    float4 bPre[4];
    bool   bAct[4];
    int    aM[5], aK[5], bN[4], bKg[4];
    #pragma unroll
    for (int l = 0; l < 5; l++) {
        int idx = tid + l * GTH;
        aM[l] = idx / BK; aK[l] = idx % BK;
    }
    #pragma unroll
    for (int l = 0; l < 4; l++) {
        int slot = tid + l * GTH;
        bAct[l] = slot < BN * (BK / 4);
        bN[l] = slot % BN; bKg[l] = slot / BN;
    }

    // load tile 0
    #pragma unroll
    for (int l = 0; l < 5; l++)
        aPre[l] = IN[(long long)(m0 + aM[l]) * IDIM + aK[l]];
    #pragma unroll
    for (int l = 0; l < 4; l++) {
        float4 v = make_float4(0.f, 0.f, 0.f, 0.f);
        int gn = n0 + bN[l];
        if (bAct[l] && gn < HDIM)
            v = *(const float4*)&Wih[(long long)gn * IDIM + bKg[l] * 4];
        bPre[l] = v;
    }

    for (int it = 0; it < NKT; it++) {
        __syncthreads();   // previous tile's consumers done
        #pragma unroll
        for (int l = 0; l < 5; l++) As[aK[l]][aM[l]] = aPre[l];
        #pragma unroll
        for (int l = 0; l < 4; l++) {
            if (bAct[l]) {
                Bs[bKg[l] * 4 + 0][bN[l]] = bPre[l].x;
                Bs[bKg[l] * 4 + 1][bN[l]] = bPre[l].y;
                Bs[bKg[l] * 4 + 2][bN[l]] = bPre[l].z;
                Bs[bKg[l] * 4 + 3][bN[l]] = bPre[l].w;
            }
        }
        __syncthreads();   // tile ready

        if (it + 1 < NKT) {   // prefetch next tile (hidden under FFMA below)
            int kk = (it + 1) * BK;
            #pragma unroll
            for (int l = 0; l < 5; l++)
                aPre[l] = IN[(long long)(m0 + aM[l]) * IDIM + kk + aK[l]];
            #pragma unroll
            for (int l = 0; l < 4; l++) {
                float4 v = make_float4(0.f, 0.f, 0.f, 0.f);
                int gn = n0 + bN[l];
                if (bAct[l] && gn < HDIM)
                    v = *(const float4*)&Wih[(long long)gn * IDIM + kk + bKg[l] * 4];
                bPre[l] = v;
            }
        }

        #pragma unroll
        for (int k = 0; k < BK; k++) {
            float4 av = *(const float4*)&As[k][tm0];
            unsigned long long b0 = *(const unsigned long long*)&Bs[k][tn0];
            unsigned long long b1 = *(const unsigned long long*)&Bs[k][tn0 + 32];
            unsigned long long b2 = *(const unsigned long long*)&Bs[k][tn0 + 64];
            unsigned long long b3 = *(const unsigned long long*)&Bs[k][tn0 + 96];
            unsigned long long b4 = *(const unsigned long long*)&Bs[k][tn0 + 128];
            unsigned long long a0 = bcast2(av.x), a1 = bcast2(av.y);
            unsigned long long a2 = bcast2(av.z), a3 = bcast2(av.w);
            ffma2(acc[0][0], a0, b0); ffma2(acc[0][1], a0, b1); ffma2(acc[0][2], a0, b2);
            ffma2(acc[0][3], a0, b3); ffma2(acc[0][4], a0, b4);
            ffma2(acc[1][0], a1, b0); ffma2(acc[1][1], a1, b1); ffma2(acc[1][2], a1, b2);
            ffma2(acc[1][3], a1, b3); ffma2(acc[1][4], a1, b4);
            ffma2(acc[2][0], a2, b0); ffma2(acc[2][1], a2, b1); ffma2(acc[2][2], a2, b2);
            ffma2(acc[2][3], a2, b3); ffma2(acc[2][4], a2, b4);
            ffma2(acc[3][0], a3, b0); ffma2(acc[3][1], a3, b1); ffma2(acc[3][2], a3, b2);
            ffma2(acc[3][3], a3, b3); ffma2(acc[3][4], a3, b4);
        }
    }
    float bias[10];
    #pragma unroll
    for (int u = 0; u < 5; u++) {
        int gn = n0 + tn0 + 32 * u;
        bias[2 * u]     = (gn < HDIM)     ? (bih[gn] + bhh[gn])         : 0.f;
        bias[2 * u + 1] = (gn + 1 < HDIM) ? (bih[gn + 1] + bhh[gn + 1]) : 0.f;
    }
    #pragma unroll
    for (int i = 0; i < 4; i++) {
        long long row = (long long)(m0 + tm0 + i) * NP + n0 + tn0;
        #pragma unroll
        for (int u = 0; u < 5; u++) {
            float lo, hi; unpack2(acc[i][u], lo, hi);
            float2 v = make_float2(lo + bias[2 * u], hi + bias[2 * u + 1]);
            *(float2*)&g_XP[row + 32 * u] = v;
        }
    }
}

// -------- recurrent scan: 64 clusters x 2 CTAs, 8 batch per cluster --------
// R12 structure (permuted-k, 2j x 4b x 76k, full-parallel tail, dsmem_st64 +
// single release-arrive) + XPS staging with CORRECT placement: the coalesced
// xp LDG issues at the top of the step, but the STS to XPS happens AFTER the
// MAC loop (R15 stored immediately after the LDG, exposing ~600cyc DRAM
// latency per warp per step before the MAC — that was the 1.49->1.67 ms
// regression). Consumers read XPS after the existing pre-reduce sync.
__global__ __cluster_dims__(2, 1, 1) __launch_bounds__(STH, 1)
void scan_kernel(const float* __restrict__ Whh, float* __restrict__ out) {
    extern __shared__ float sm[];
    float* WT = sm;                                           // [304][152] permuted-k
    float* H  = sm + WSZ;                                     // [2][304][8]
    unsigned long long* PART = (unsigned long long*)(H + 2 * HB);  // [4][PSTR]
    float* XPS = (float*)(PART + 4 * PSTR);                   // [8][XSTR]
    unsigned long long* mbarp = (unsigned long long*)(XPS + 8 * XSTR);

    int tid = threadIdx.x;
    unsigned rank;
    asm("mov.u32 %0, %%cluster_ctarank;" : "=r"(rank));
    int cid = blockIdx.x >> 1;
    unsigned peer = rank ^ 1u;

    if (tid == 0) {
        asm volatile("mbarrier.init.shared.b64 [%0], 1;"
                     :: "r"(smem_u32(mbarp)) : "memory");
    }
    // WT[kloc][j] = Whh[rank*152+j][kglob]; kloc<152 own k, >=152 peer k
    for (int idx = tid; idx < JH * KROWS; idx += STH) {
        int j = idx / KROWS, kloc = idx % KROWS;
        int jg = rank * JH + j;
        int kg = (kloc < JH) ? (rank * JH + kloc) : (peer * JH + (kloc - JH));
        float v = 0.f;
        if (jg < HDIM && kg < HDIM) v = Whh[(long long)jg * HDIM + kg];
        WT[kloc * JH + j] = v;
    }
    for (int i = tid; i < 2 * HB; i += STH) H[i] = 0.f;

    // MAC-role indices: tid = kq*152 + jp*2 + half
    int kq = tid / 152, lid2 = tid % 152;
    int jp = lid2 >> 1, half = lid2 & 1;
    int j0 = jp * 2;
    int kstart = kq * SKCH;
    const float* Wp0 = WT + kstart * JH + j0;
    bool remote_warp = (tid >> 5) >= 9;      // warps with kq>=2 lanes

    // reduce-role indices: one u64 output (row j_out, batch pair bq)
    int j_out = tid >> 2, bq = tid & 3;
    int lid2_s = (j_out >> 1) * 2 + (bq >> 1);   // producer lane within kq block
    int s_slot = (j_out & 1) * 2 + (bq & 1);     // producer acc slot

    // XPS loader role: batch lb (0..7), j-pair lj (coalesced float2 LDG)
    int lb = tid / 76, lj = tid % 76;
    const float* xldg = g_XP + (long long)(cid * 8 + lb) * NP + rank * JH + lj * 2;
    float* xsts = XPS + lb * XSTR + lj * 2;

    uint32_t hbase32 = smem_u32(H);
    uint32_t mbar32 = smem_u32(mbarp);

    __syncthreads();
    asm volatile("barrier.cluster.arrive.aligned;" ::: "memory");
    asm volatile("barrier.cluster.wait.aligned;" ::: "memory");

    int p = 0;
    for (int t = 0; t < SEQ; t++) {
        // issue coalesced xp LDG now; consumed (stored to XPS) after the MAC
        float2 xv = *(const float2*)(xldg + (long long)t * BATCH * NP);

        // remote warps wait for peer's step-(t-1) h-half; local warps proceed
        if (t > 0 && remote_warp) {
            unsigned ph = (unsigned)((t - 1) & 1);
            uint32_t done;
            asm volatile("{ .reg .pred p; "
                         "mbarrier.try_wait.parity.acquire.cluster.shared::cta.b64 p, [%1], %2; "
                         "selp.b32 %0, 1, 0, p; }"
                         : "=r"(done) : "r"(mbar32), "r"(ph) : "memory");
            if (!done) {
                asm volatile("{ .reg .pred P1; "
                             "WL%=: mbarrier.try_wait.parity.acquire.cluster.shared::cta.b64 P1, [%0], %1, 0x989680; "
                             "@P1 bra.uni WD%=; bra.uni WL%=; WD%=: }"
                             :: "r"(mbar32), "r"(ph) : "memory");
            }
        }

        // MAC over this thread's k-quarter (2j x 4b x 76k)
        unsigned long long A00 = 0, A01 = 0, A10 = 0, A11 = 0;
        const float* Wp = Wp0;
        const float* hp = H + p * HB + kstart * 8 + half * 4;
        #pragma unroll 4
        for (int kk = 0; kk < SKCH; kk++) {
            float2 w = *(const float2*)(Wp + kk * JH);
            ulonglong2 hv = *(const ulonglong2*)(hp + kk * 8);
            unsigned long long w0 = bcast2(w.x);
            unsigned long long w1 = bcast2(w.y);
            ffma2(A00, w0, hv.x); ffma2(A01, w0, hv.y);
            ffma2(A10, w1, hv.x); ffma2(A11, w1, hv.y);
        }
        // xp store deferred to here: LDG latency hidden under the MAC loop
        *(float2*)xsts = xv;
        PART[0 * PSTR + tid] = A00;
        PART[1 * PSTR + tid] = A01;
        PART[2 * PSTR + tid] = A10;
        PART[3 * PSTR + tid] = A11;
        __syncthreads();

        // reduce 4 k-quarter partials for output (j_out, batches 2bq, 2bq+1)
        const unsigned long long* src = PART + s_slot * PSTR + lid2_s;
        unsigned long long acc = src[0];
        fadd2(acc, src[152]);
        fadd2(acc, src[304]);
        fadd2(acc, src[456]);
        float x0 = XPS[(bq * 2) * XSTR + j_out];
        float x1 = XPS[(bq * 2 + 1) * XSTR + j_out];
        float v0, v1;
        unpack2(acc, v0, v1);
        float h0 = fast_tanh(x0 + v0);
        float h1 = fast_tanh(x1 + v1);
        int off = (1 - p) * HB + j_out * 8 + bq * 2;          // own region row
        *(float2*)(H + off) = make_float2(h0, h1);
        uint32_t rdst = hbase32 + ((1 - p) * HB + (JH + j_out) * 8 + bq * 2) * 4;
        dsmem_st64(rdst, peer, h0, h1);                       // peer's [152+j] row

        __syncthreads();   // local H writes + DSMEM stores ordered before arrive
        if (tid == 0) {
            asm volatile("{ .reg .b32 pa; mapa.shared::cluster.u32 pa, %0, %1; "
                         "mbarrier.arrive.release.cluster.shared::cluster.b64 _, [pa]; }"
                         :: "r"(mbar32), "r"(peer) : "memory");
        }
        p ^= 1;
    }

    // final h: own rows [0,152) of H[p] -> out
    const float* Hf = H + p * HB;
    int cb0 = cid * 8;
    for (int idx = tid; idx < 8 * JH; idx += STH) {
        int b = idx / JH, jj = idx % JH;
        int j = rank * JH + jj;
        if (j < HDIM) out[(long long)(cb0 + b) * HDIM + j] = Hf[jj * 8 + b];
    }
    asm volatile("barrier.cluster.arrive.aligned;" ::: "memory");
    asm volatile("barrier.cluster.wait.aligned;" ::: "memory");
}

extern "C" void kernel_launch(void* const* d_in, const int* in_sizes, int n_in,
                              void* d_out, int out_size) {
    const float* IN  = (const float*)d_in[0];
    const float* Wih = (const float*)d_in[1];
    const float* Whh = (const float*)d_in[2];
    const float* bih = (const float*)d_in[3];
    const float* bhh = (const float*)d_in[4];
    float* out = (float*)d_out;

    dim3 g(NP / BN, MTOT / BM);   // (2, 4096)
    gemm_xproj<<<g, GTH>>>(IN, Wih, bih, bhh);

    // smem: WT 184832 + H 19456 + PART 19584 + XPS 4928 + mbar 8 = 228808 B
    size_t smem = (size_t)WSZ * 4 + (size_t)2 * HB * 4 + (size_t)4 * PSTR * 8
                + (size_t)8 * XSTR * 4 + 8;
    cudaFuncSetAttribute(scan_kernel, cudaFuncAttributeMaxDynamicSharedMemorySize, (int)smem);
    scan_kernel<<<128, STH, smem>>>(Whh, out);
}